// round 1
// baseline (speedup 1.0000x reference)
#include <cuda_runtime.h>
#include <math.h>

// Problem constants
#define B_   2
#define S_   2048
#define H_   2048
#define NH_  16
#define HD_  128
#define M_   (B_ * S_)      // 4096 rows of the "token" matrix
#define NQKV (3 * H_)       // 6144

// ---------------------------------------------------------------------------
// Scratch (device globals — allocation-free per harness rules)
// ---------------------------------------------------------------------------
__device__ __align__(256) float g_qkv[(size_t)M_ * NQKV];            // 100.7 MB
__device__ __align__(256) float g_q[(size_t)B_ * NH_ * S_ * HD_];    // 33.6 MB
__device__ __align__(256) float g_k[(size_t)B_ * NH_ * S_ * HD_];
__device__ __align__(256) float g_v[(size_t)B_ * NH_ * S_ * HD_];
__device__ __align__(256) float g_attn[(size_t)B_ * NH_ * S_ * HD_];
__device__ __align__(256) float g_ctx[(size_t)M_ * H_];              // 33.6 MB
__device__ __align__(256) float g_cos[S_ * 64];
__device__ __align__(256) float g_sin[S_ * 64];

// ---------------------------------------------------------------------------
// RoPE trig table. Emulates the jax fp32 phase (theta rounded to fp32), then
// evaluates cos/sin accurately in double.
// ---------------------------------------------------------------------------
__global__ void trig_kernel() {
    int idx = blockIdx.x * blockDim.x + threadIdx.x;
    if (idx >= S_ * 64) return;
    int s = idx >> 6, i = idx & 63;
    float invf = (float)pow(10000.0, -(double)i / 64.0);
    float th = (float)s * invf;                 // fp32 phase, like the reference
    g_cos[idx] = (float)cos((double)th);
    g_sin[idx] = (float)sin((double)th);
}

// ---------------------------------------------------------------------------
// SGEMM: C[M,N] = A[M,K] @ B[K,N], all row-major fp32.
// 128x128 tile, K-step 8, 256 threads, 8x8 microtile (cols split 4+4 at +64
// for conflict-free LDS.128 on the B tile).
// Requires M%128==0, N%128==0, K%8==0 (true for all our shapes).
// ---------------------------------------------------------------------------
__global__ __launch_bounds__(256) void sgemm_kernel(
    const float* __restrict__ A, const float* __restrict__ Bm,
    float* __restrict__ C, int M, int N, int K)
{
    __shared__ float As[8][128];   // transposed: As[k][m]
    __shared__ float Bs[8][128];

    const int tid = threadIdx.x;
    const int tx = tid & 15;           // 0..15 -> column quad
    const int ty = tid >> 4;           // 0..15 -> row octet
    const int row0 = blockIdx.y * 128;
    const int col0 = blockIdx.x * 128;

    // A tile load: thread -> one float4 (row = tid/2, k4 = (tid&1)*4)
    const int a_row = tid >> 1;
    const int a_k4  = (tid & 1) * 4;
    // B tile load: thread -> one float4 (k = tid/32, col4 = (tid&31)*4)
    const int b_k  = tid >> 5;
    const int b_c4 = (tid & 31) * 4;

    const float* Aptr = A + (size_t)(row0 + a_row) * K + a_k4;
    const float* Bptr = Bm + (size_t)b_k * N + col0 + b_c4;

    float acc[8][8];
    #pragma unroll
    for (int i = 0; i < 8; i++)
        #pragma unroll
        for (int j = 0; j < 8; j++) acc[i][j] = 0.f;

    for (int k0 = 0; k0 < K; k0 += 8) {
        float4 av = *(const float4*)(Aptr + k0);
        float4 bv = *(const float4*)(Bptr + (size_t)k0 * N);
        As[a_k4 + 0][a_row] = av.x;
        As[a_k4 + 1][a_row] = av.y;
        As[a_k4 + 2][a_row] = av.z;
        As[a_k4 + 3][a_row] = av.w;
        *(float4*)&Bs[b_k][b_c4] = bv;
        __syncthreads();

        #pragma unroll
        for (int kk = 0; kk < 8; kk++) {
            float4 a0 = *(float4*)&As[kk][ty * 8];
            float4 a1 = *(float4*)&As[kk][ty * 8 + 4];
            float4 b0 = *(float4*)&Bs[kk][tx * 4];
            float4 b1 = *(float4*)&Bs[kk][64 + tx * 4];
            float ar[8] = {a0.x, a0.y, a0.z, a0.w, a1.x, a1.y, a1.z, a1.w};
            float br[8] = {b0.x, b0.y, b0.z, b0.w, b1.x, b1.y, b1.z, b1.w};
            #pragma unroll
            for (int i = 0; i < 8; i++)
                #pragma unroll
                for (int j = 0; j < 8; j++)
                    acc[i][j] = fmaf(ar[i], br[j], acc[i][j]);
        }
        __syncthreads();
    }

    #pragma unroll
    for (int i = 0; i < 8; i++) {
        float* Crow = C + (size_t)(row0 + ty * 8 + i) * N + col0;
        *(float4*)(Crow + tx * 4)      = make_float4(acc[i][0], acc[i][1], acc[i][2], acc[i][3]);
        *(float4*)(Crow + 64 + tx * 4) = make_float4(acc[i][4], acc[i][5], acc[i][6], acc[i][7]);
    }
}

// ---------------------------------------------------------------------------
// Split qkv [b,s,3,nh,hd] -> Q/K/V [b,nh,s,hd] with RoPE applied to Q,K.
// One thread per (b,nh,s,d) with d<64 handles the rotation pair (d, d+64).
// ---------------------------------------------------------------------------
__global__ void split_rope_kernel() {
    int idx = blockIdx.x * blockDim.x + threadIdx.x;   // < 2^22
    int d  = idx & 63;
    int s  = (idx >> 6) & 2047;
    int nh = (idx >> 17) & 15;
    int b  = idx >> 21;

    size_t in = (size_t)(b * S_ + s) * NQKV + nh * HD_;
    float c  = g_cos[s * 64 + d];
    float sn = g_sin[s * 64 + d];
    float q1 = g_qkv[in + d],            q2 = g_qkv[in + d + 64];
    float k1 = g_qkv[in + H_ + d],       k2 = g_qkv[in + H_ + d + 64];
    float v1 = g_qkv[in + 2 * H_ + d],   v2 = g_qkv[in + 2 * H_ + d + 64];

    size_t out = ((size_t)(b * NH_ + nh) * S_ + s) * HD_;
    g_q[out + d]      = q1 * c - q2 * sn;
    g_q[out + d + 64] = q2 * c + q1 * sn;
    g_k[out + d]      = k1 * c - k2 * sn;
    g_k[out + d + 64] = k2 * c + k1 * sn;
    g_v[out + d]      = v1;
    g_v[out + d + 64] = v2;
}

// ---------------------------------------------------------------------------
// Causal flash attention. Grid: (S/64 q-tiles [reversed for load balance],
// B*NH). 256 threads; a 4-lane quad owns one query row; lane `sub` owns the
// interleaved dims {4*sub+16*i .. +3}, which makes all smem float4 reads
// bank-conflict-free. Online softmax, K-tile = 32 keys.
// ---------------------------------------------------------------------------
__global__ __launch_bounds__(256) void attn_kernel() {
    const int bh  = blockIdx.y;
    const int q0  = (gridDim.x - 1 - blockIdx.x) * 64;  // heavy tiles first
    const int tid = threadIdx.x;
    const int grp = tid >> 2;
    const int sub = tid & 3;
    const int qi  = q0 + grp;

    __shared__ float4 Ks[32 * 32];   // 32 keys x 128 dims
    __shared__ float4 Vs[32 * 32];

    const float4* Q4 = (const float4*)g_q;
    const float4* K4 = (const float4*)g_k;
    const float4* V4 = (const float4*)g_v;
    float4*       O4 = (float4*)g_attn;

    const size_t qbase = ((size_t)bh * S_ + qi) * 32;
    float4 q[8];
    #pragma unroll
    for (int i = 0; i < 8; i++) q[i] = Q4[qbase + sub + 4 * i];

    float4 acc[8];
    #pragma unroll
    for (int i = 0; i < 8; i++) acc[i] = make_float4(0.f, 0.f, 0.f, 0.f);
    float m = -1e30f, l = 0.f;
    const float scale = 0.08838834764831845f;   // 1/sqrt(128)

    const int ntiles = (q0 + 64) / 32;
    for (int kt = 0; kt < ntiles; kt++) {
        const int k0 = kt * 32;
        #pragma unroll
        for (int r = 0; r < 4; r++) {
            int idx = tid + 256 * r;            // 0..1023
            int row = idx >> 5, c = idx & 31;
            size_t gsrc = ((size_t)bh * S_ + k0 + row) * 32 + c;
            Ks[idx] = K4[gsrc];
            Vs[idx] = V4[gsrc];
        }
        __syncthreads();

        // scores (each quad computes all 32, lane keeps k = 4j+sub)
        float sloc[8];
        #pragma unroll
        for (int kk = 0; kk < 32; kk++) {
            float ps = 0.f;
            #pragma unroll
            for (int i = 0; i < 8; i++) {
                float4 kv = Ks[kk * 32 + sub + 4 * i];
                ps = fmaf(q[i].x, kv.x, ps);
                ps = fmaf(q[i].y, kv.y, ps);
                ps = fmaf(q[i].z, kv.z, ps);
                ps = fmaf(q[i].w, kv.w, ps);
            }
            ps += __shfl_xor_sync(0xffffffffu, ps, 1);
            ps += __shfl_xor_sync(0xffffffffu, ps, 2);
            float s = ps * scale;
            if (k0 + kk > qi) s = -1e30f;       // causal mask
            if ((kk & 3) == sub) sloc[kk >> 2] = s;
        }

        // online softmax update
        float tmax = sloc[0];
        #pragma unroll
        for (int j = 1; j < 8; j++) tmax = fmaxf(tmax, sloc[j]);
        tmax = fmaxf(tmax, __shfl_xor_sync(0xffffffffu, tmax, 1));
        tmax = fmaxf(tmax, __shfl_xor_sync(0xffffffffu, tmax, 2));
        float mnew = fmaxf(m, tmax);
        float corr = __expf(m - mnew);
        m = mnew;
        l *= corr;
        #pragma unroll
        for (int i = 0; i < 8; i++) {
            acc[i].x *= corr; acc[i].y *= corr;
            acc[i].z *= corr; acc[i].w *= corr;
        }
        float p[8];
        #pragma unroll
        for (int j = 0; j < 8; j++) { p[j] = __expf(sloc[j] - m); l += p[j]; }

        // PV accumulate (p broadcast within the 4-lane quad)
        #pragma unroll
        for (int kk = 0; kk < 32; kk++) {
            float pv = __shfl_sync(0xffffffffu, p[kk >> 2], kk & 3, 4);
            #pragma unroll
            for (int i = 0; i < 8; i++) {
                float4 vv = Vs[kk * 32 + sub + 4 * i];
                acc[i].x = fmaf(pv, vv.x, acc[i].x);
                acc[i].y = fmaf(pv, vv.y, acc[i].y);
                acc[i].z = fmaf(pv, vv.z, acc[i].z);
                acc[i].w = fmaf(pv, vv.w, acc[i].w);
            }
        }
        __syncthreads();
    }

    l += __shfl_xor_sync(0xffffffffu, l, 1);
    l += __shfl_xor_sync(0xffffffffu, l, 2);
    float inv = 1.f / l;
    #pragma unroll
    for (int i = 0; i < 8; i++) {
        float4 o = make_float4(acc[i].x * inv, acc[i].y * inv,
                               acc[i].z * inv, acc[i].w * inv);
        O4[qbase + sub + 4 * i] = o;
    }
}

// ---------------------------------------------------------------------------
// attn_out [b,nh,s,hd] -> ctx [b,s,h]  (h = nh*128 + d). float4 copies,
// coalesced on both sides.
// ---------------------------------------------------------------------------
__global__ void transpose_kernel() {
    int idx = blockIdx.x * blockDim.x + threadIdx.x;   // < M_*H_/4
    int col4 = idx & 511;              // H_/4 = 512
    int row  = idx >> 9;
    int b = row >> 11, s = row & 2047;
    int nh = col4 >> 5, d4 = col4 & 31;
    ((float4*)g_ctx)[idx] =
        ((const float4*)g_attn)[((size_t)(b * NH_ + nh) * S_ + s) * 32 + d4];
}

// ---------------------------------------------------------------------------
// kernel_launch
// inputs: [0]=input_tensor fp32 [B,S,H], [1]=attention_mask (unused; it is
// exactly the causal mask, applied analytically), [2]=Wqkv fp32 [H,3H],
// [3]=Wo fp32 [H,H]. out: fp32 [B,S,H].
// ---------------------------------------------------------------------------
extern "C" void kernel_launch(void* const* d_in, const int* in_sizes, int n_in,
                              void* d_out, int out_size)
{
    const float* x    = (const float*)d_in[0];
    const float* wqkv = (const float*)d_in[2];
    const float* wo   = (const float*)d_in[3];

    float *qkv_ptr, *ctx_ptr;
    cudaGetSymbolAddress((void**)&qkv_ptr, g_qkv);
    cudaGetSymbolAddress((void**)&ctx_ptr, g_ctx);

    trig_kernel<<<(S_ * 64 + 255) / 256, 256>>>();
    sgemm_kernel<<<dim3(NQKV / 128, M_ / 128), 256>>>(x, wqkv, qkv_ptr, M_, NQKV, H_);
    split_rope_kernel<<<(B_ * NH_ * S_ * 64) / 256, 256>>>();
    attn_kernel<<<dim3(S_ / 64, B_ * NH_), 256>>>();
    transpose_kernel<<<(M_ * H_ / 4) / 256, 256>>>();
    sgemm_kernel<<<dim3(H_ / 128, M_ / 128), 256>>>(ctx_ptr, wo, (float*)d_out, M_, H_, H_);
}

// round 6
// speedup vs baseline: 1.9699x; 1.9699x over previous
#include <cuda_runtime.h>
#include <cuda_bf16.h>
#include <cstdint>
#include <math.h>

// Problem constants
#define B_   2
#define S_   2048
#define H_   2048
#define NH_  16
#define HD_  128
#define M_   (B_ * S_)      // 4096
#define NQKV (3 * H_)       // 6144

// ---------------------------------------------------------------------------
// Scratch (device globals — allocation-free per harness rules)
// ---------------------------------------------------------------------------
__device__ __align__(256) float g_qkv[(size_t)M_ * NQKV];
__device__ __align__(256) float g_q[(size_t)B_ * NH_ * S_ * HD_];
__device__ __align__(256) float g_k[(size_t)B_ * NH_ * S_ * HD_];
__device__ __align__(256) float g_v[(size_t)B_ * NH_ * S_ * HD_];
__device__ __align__(256) float g_attn[(size_t)B_ * NH_ * S_ * HD_];
__device__ __align__(256) float g_ctx[(size_t)M_ * H_];
__device__ __align__(256) float g_wqkvT[(size_t)NQKV * H_];   // Wqkv^T [6144,2048]
__device__ __align__(256) float g_woT[(size_t)H_ * H_];       // Wo^T   [2048,2048]
__device__ __align__(256) float g_cos[S_ * 64];
__device__ __align__(256) float g_sin[S_ * 64];

// ---------------------------------------------------------------------------
// fp32 -> (hi, lo) bf16 split, 2 floats at a time, packed bf16x2
// ---------------------------------------------------------------------------
__device__ __forceinline__ void split2(float a, float b, uint32_t& hi, uint32_t& lo) {
    __nv_bfloat162 h = __floats2bfloat162_rn(a, b);
    float ra = a - __bfloat162float(h.x);
    float rb = b - __bfloat162float(h.y);
    __nv_bfloat162 l = __floats2bfloat162_rn(ra, rb);
    hi = *(uint32_t*)&h;
    lo = *(uint32_t*)&l;
}

// mma.sync m16n8k16 bf16 (row.col), fp32 accumulate — sm_80+ path, legal on
// the harness's compute_103 PTX target (tcgen05 is NOT: needs sm_103a).
#define MMA16816(cr, a, b0r, b1r)                                             \
    asm volatile("mma.sync.aligned.m16n8k16.row.col.f32.bf16.bf16.f32 "       \
        "{%0,%1,%2,%3}, {%4,%5,%6,%7}, {%8,%9}, {%0,%1,%2,%3};"               \
        : "+f"((cr)[0]), "+f"((cr)[1]), "+f"((cr)[2]), "+f"((cr)[3])          \
        : "r"((a).x), "r"((a).y), "r"((a).z), "r"((a).w), "r"(b0r), "r"(b1r))

// ---------------------------------------------------------------------------
// RoPE trig table (fp32 phase to match jax, accurate trig)
// ---------------------------------------------------------------------------
__global__ void trig_kernel() {
    int idx = blockIdx.x * blockDim.x + threadIdx.x;
    if (idx >= S_ * 64) return;
    int s = idx >> 6, i = idx & 63;
    float invf = (float)pow(10000.0, -(double)i / 64.0);
    float th = (float)s * invf;
    g_cos[idx] = (float)cos((double)th);
    g_sin[idx] = (float)sin((double)th);
}

// ---------------------------------------------------------------------------
// Weight transpose: W[K,N] -> WT[N,K]
// ---------------------------------------------------------------------------
__global__ void wtrans_kernel(const float* __restrict__ W, float* __restrict__ WT,
                              int K, int N) {
    __shared__ float t[32][33];
    int k0 = blockIdx.x * 32, n0 = blockIdx.y * 32;
    int tx = threadIdx.x, ty = threadIdx.y;     // 32 x 8
    #pragma unroll
    for (int j = 0; j < 4; j++)
        t[ty + 8 * j][tx] = W[(size_t)(k0 + ty + 8 * j) * N + n0 + tx];
    __syncthreads();
    #pragma unroll
    for (int j = 0; j < 4; j++)
        WT[(size_t)(n0 + ty + 8 * j) * K + k0 + tx] = t[tx][ty + 8 * j];
}

// ---------------------------------------------------------------------------
// Split-precision bf16 mma.sync GEMM.
// C[M,N] = A[M,K] @ W[K,N], W passed pre-transposed as BT[N,K] (K contiguous).
// CTA tile 128x128, 256 threads (8 warps, warp grid 4(M) x 2(N), warp tile
// 32x64), K-step 32. hi/lo bf16 split, terms hh + hl + lh.
//
// Smem holds fragments PRE-PERMUTED to the documented m16n8k16 per-thread
// layout: A slab = [tile_m(8) x tile_k(2)][lane(32)] x 16B  (one LDS.128 =
// the full 4-reg A fragment), B slab = [tile_n(16) x tile_k(2)][lane] x 8B.
// All fragment loads are conflict-free by construction.
// ---------------------------------------------------------------------------
__global__ __launch_bounds__(256, 2) void gemm_bf16s(
    const float* __restrict__ A, const float* __restrict__ BT,
    float* __restrict__ C, int M, int N, int K)
{
    // words: [Ahi 2048][Alo 2048][Bhi 2048][Blo 2048] = 32 KB
    __shared__ uint32_t sh[8192];

    const int tid = threadIdx.x;
    const int wid = tid >> 5, lane = tid & 31;
    const int g = lane >> 2, tig = lane & 3;
    const int warp_m = wid >> 1, warp_n = wid & 1;
    const int row0 = blockIdx.y * 128, col0 = blockIdx.x * 128;

    float c[2][8][4] = {};

    for (int k0 = 0; k0 < K; k0 += 32) {
        __syncthreads();
        // A tile 128x32: 4 float4 per thread, split + permuted store
        #pragma unroll
        for (int u = 0; u < 4; u++) {
            int idx = tid + 256 * u;            // 0..1023
            int m = idx >> 3, cseg = idx & 7;   // klocal = 4*cseg
            float4 v = *(const float4*)(A + (size_t)(row0 + m) * K + k0 + cseg * 4);
            uint32_t h0, l0, h1, l1;
            split2(v.x, v.y, h0, l0);
            split2(v.z, v.w, h1, l1);
            int kl = cseg * 4;
            int tile_m = m >> 4, half_m = (m >> 3) & 1, gg = m & 7;
            int tile_k = kl >> 4, kk = kl & 15, half_k = kk >> 3, tg = (kk & 7) >> 1;
            int reg = half_m + 2 * half_k;
            int base = ((tile_m * 2 + tile_k) * 32 + gg * 4 + tg) * 4 + reg;
            sh[base] = h0;        sh[base + 4] = h1;        // next tig lane
            sh[2048 + base] = l0; sh[2048 + base + 4] = l1;
        }
        // B tile 128x32 from BT rows
        #pragma unroll
        for (int u = 0; u < 4; u++) {
            int idx = tid + 256 * u;
            int n = idx >> 3, cseg = idx & 7;
            float4 v = *(const float4*)(BT + (size_t)(col0 + n) * K + k0 + cseg * 4);
            uint32_t h0, l0, h1, l1;
            split2(v.x, v.y, h0, l0);
            split2(v.z, v.w, h1, l1);
            int kl = cseg * 4;
            int tile_n = n >> 3, gg = n & 7;
            int tile_k = kl >> 4, kk = kl & 15, reg = kk >> 3, tg = (kk & 7) >> 1;
            int base = ((tile_n * 2 + tile_k) * 32 + gg * 4 + tg) * 2 + reg;
            sh[4096 + base] = h0; sh[4096 + base + 2] = h1;
            sh[6144 + base] = l0; sh[6144 + base + 2] = l1;
        }
        __syncthreads();

        #pragma unroll
        for (int tk = 0; tk < 2; tk++) {
            uint4 ahi[2], alo[2];
            #pragma unroll
            for (int i = 0; i < 2; i++) {
                int off = (((warp_m * 2 + i) * 2 + tk) * 32 + lane) * 4;
                ahi[i] = *(uint4*)&sh[off];
                alo[i] = *(uint4*)&sh[2048 + off];
            }
            #pragma unroll
            for (int j = 0; j < 8; j++) {
                int off = (((warp_n * 8 + j) * 2 + tk) * 32 + lane) * 2;
                uint32_t bh0 = sh[4096 + off], bh1 = sh[4096 + off + 1];
                uint32_t bl0 = sh[6144 + off], bl1 = sh[6144 + off + 1];
                #pragma unroll
                for (int i = 0; i < 2; i++) {
                    MMA16816(c[i][j], ahi[i], bh0, bh1);   // hh
                    MMA16816(c[i][j], ahi[i], bl0, bl1);   // hl
                    MMA16816(c[i][j], alo[i], bh0, bh1);   // lh
                }
            }
        }
    }

    // epilogue: c-frag rows g / g+8, cols 2*tig within each (m16, n8) tile
    #pragma unroll
    for (int i = 0; i < 2; i++) {
        int r0 = row0 + (warp_m * 2 + i) * 16 + g;
        #pragma unroll
        for (int j = 0; j < 8; j++) {
            int cc = col0 + (warp_n * 8 + j) * 8 + tig * 2;
            *(float2*)(C + (size_t)r0 * N + cc)       = make_float2(c[i][j][0], c[i][j][1]);
            *(float2*)(C + (size_t)(r0 + 8) * N + cc) = make_float2(c[i][j][2], c[i][j][3]);
        }
    }
}

// ---------------------------------------------------------------------------
// Split qkv [b,s,3,nh,hd] -> Q/K/V [b,nh,s,hd] with RoPE on Q,K.
// ---------------------------------------------------------------------------
__global__ void split_rope_kernel() {
    int idx = blockIdx.x * blockDim.x + threadIdx.x;
    int d  = idx & 63;
    int s  = (idx >> 6) & 2047;
    int nh = (idx >> 17) & 15;
    int b  = idx >> 21;

    size_t in = (size_t)(b * S_ + s) * NQKV + nh * HD_;
    float c  = g_cos[s * 64 + d];
    float sn = g_sin[s * 64 + d];
    float q1 = g_qkv[in + d],          q2 = g_qkv[in + d + 64];
    float k1 = g_qkv[in + H_ + d],     k2 = g_qkv[in + H_ + d + 64];
    float v1 = g_qkv[in + 2 * H_ + d], v2 = g_qkv[in + 2 * H_ + d + 64];

    size_t out = ((size_t)(b * NH_ + nh) * S_ + s) * HD_;
    g_q[out + d]      = q1 * c - q2 * sn;
    g_q[out + d + 64] = q2 * c + q1 * sn;
    g_k[out + d]      = k1 * c - k2 * sn;
    g_k[out + d + 64] = k2 * c + k1 * sn;
    g_v[out + d]      = v1;
    g_v[out + d + 64] = v2;
}

// ---------------------------------------------------------------------------
// Causal flash attention, 2 query rows per 4-lane quad (halves LDS traffic
// vs R1, which measured 80.4% L1-bound). Grid: (S/128 reversed, B*NH).
// ---------------------------------------------------------------------------
__global__ __launch_bounds__(256, 1) void attn_kernel() {
    const int bh  = blockIdx.y;
    const int q0  = (int)(gridDim.x - 1 - blockIdx.x) * 128;   // heavy first
    const int tid = threadIdx.x;
    const int grp = tid >> 2;
    const int sub = tid & 3;
    const int qa  = q0 + 2 * grp;
    const int qb  = qa + 1;

    __shared__ float4 Ks[1024];   // 32 keys x 128 dims
    __shared__ float4 Vs[1024];

    const float4* Q4 = (const float4*)g_q;
    const float4* K4 = (const float4*)g_k;
    const float4* V4 = (const float4*)g_v;
    float4*       O4 = (float4*)g_attn;

    const size_t ba = ((size_t)bh * S_ + qa) * 32;
    const size_t bb = ba + 32;
    float4 qra[8], qrb[8];
    #pragma unroll
    for (int i = 0; i < 8; i++) { qra[i] = Q4[ba + sub + 4 * i]; qrb[i] = Q4[bb + sub + 4 * i]; }

    float4 aa[8], ab[8];
    #pragma unroll
    for (int i = 0; i < 8; i++) {
        aa[i] = make_float4(0.f, 0.f, 0.f, 0.f);
        ab[i] = make_float4(0.f, 0.f, 0.f, 0.f);
    }
    float ma = -1e30f, la = 0.f, mb = -1e30f, lb = 0.f;
    const float scale = 0.08838834764831845f;   // 1/sqrt(128)

    const int ntiles = (q0 + 128) >> 5;
    for (int kt = 0; kt < ntiles; kt++) {
        const int k0 = kt << 5;
        #pragma unroll
        for (int r = 0; r < 4; r++) {
            int idx = tid + 256 * r;
            int row = idx >> 5, c = idx & 31;
            size_t gsrc = ((size_t)bh * S_ + k0 + row) * 32 + c;
            Ks[idx] = K4[gsrc];
            Vs[idx] = V4[gsrc];
        }
        __syncthreads();

        float sa[8], sb2[8];
        #pragma unroll
        for (int kk = 0; kk < 32; kk++) {
            float pa = 0.f, pb = 0.f;
            #pragma unroll
            for (int i = 0; i < 8; i++) {
                float4 kv = Ks[kk * 32 + sub + 4 * i];
                pa = fmaf(qra[i].x, kv.x, pa); pa = fmaf(qra[i].y, kv.y, pa);
                pa = fmaf(qra[i].z, kv.z, pa); pa = fmaf(qra[i].w, kv.w, pa);
                pb = fmaf(qrb[i].x, kv.x, pb); pb = fmaf(qrb[i].y, kv.y, pb);
                pb = fmaf(qrb[i].z, kv.z, pb); pb = fmaf(qrb[i].w, kv.w, pb);
            }
            pa += __shfl_xor_sync(0xffffffffu, pa, 1);
            pa += __shfl_xor_sync(0xffffffffu, pa, 2);
            pb += __shfl_xor_sync(0xffffffffu, pb, 1);
            pb += __shfl_xor_sync(0xffffffffu, pb, 2);
            float s_a = pa * scale, s_b = pb * scale;
            int kg = k0 + kk;
            if (kg > qa) s_a = -1e30f;
            if (kg > qb) s_b = -1e30f;
            if ((kk & 3) == sub) { sa[kk >> 2] = s_a; sb2[kk >> 2] = s_b; }
        }

        // online softmax, row a
        {
            float t = sa[0];
            #pragma unroll
            for (int j = 1; j < 8; j++) t = fmaxf(t, sa[j]);
            t = fmaxf(t, __shfl_xor_sync(0xffffffffu, t, 1));
            t = fmaxf(t, __shfl_xor_sync(0xffffffffu, t, 2));
            float mn = fmaxf(ma, t);
            float cr = __expf(ma - mn);
            ma = mn; la *= cr;
            #pragma unroll
            for (int i = 0; i < 8; i++) {
                aa[i].x *= cr; aa[i].y *= cr; aa[i].z *= cr; aa[i].w *= cr;
            }
            #pragma unroll
            for (int j = 0; j < 8; j++) { sa[j] = __expf(sa[j] - ma); la += sa[j]; }
        }
        // online softmax, row b
        {
            float t = sb2[0];
            #pragma unroll
            for (int j = 1; j < 8; j++) t = fmaxf(t, sb2[j]);
            t = fmaxf(t, __shfl_xor_sync(0xffffffffu, t, 1));
            t = fmaxf(t, __shfl_xor_sync(0xffffffffu, t, 2));
            float mn = fmaxf(mb, t);
            float cr = __expf(mb - mn);
            mb = mn; lb *= cr;
            #pragma unroll
            for (int i = 0; i < 8; i++) {
                ab[i].x *= cr; ab[i].y *= cr; ab[i].z *= cr; ab[i].w *= cr;
            }
            #pragma unroll
            for (int j = 0; j < 8; j++) { sb2[j] = __expf(sb2[j] - mb); lb += sb2[j]; }
        }

        // PV accumulate
        #pragma unroll
        for (int kk = 0; kk < 32; kk++) {
            float pva = __shfl_sync(0xffffffffu, sa[kk >> 2],  kk & 3, 4);
            float pvb = __shfl_sync(0xffffffffu, sb2[kk >> 2], kk & 3, 4);
            #pragma unroll
            for (int i = 0; i < 8; i++) {
                float4 vv = Vs[kk * 32 + sub + 4 * i];
                aa[i].x = fmaf(pva, vv.x, aa[i].x); aa[i].y = fmaf(pva, vv.y, aa[i].y);
                aa[i].z = fmaf(pva, vv.z, aa[i].z); aa[i].w = fmaf(pva, vv.w, aa[i].w);
                ab[i].x = fmaf(pvb, vv.x, ab[i].x); ab[i].y = fmaf(pvb, vv.y, ab[i].y);
                ab[i].z = fmaf(pvb, vv.z, ab[i].z); ab[i].w = fmaf(pvb, vv.w, ab[i].w);
            }
        }
        __syncthreads();
    }

    la += __shfl_xor_sync(0xffffffffu, la, 1);
    la += __shfl_xor_sync(0xffffffffu, la, 2);
    lb += __shfl_xor_sync(0xffffffffu, lb, 1);
    lb += __shfl_xor_sync(0xffffffffu, lb, 2);
    float ia = 1.f / la, ib = 1.f / lb;
    #pragma unroll
    for (int i = 0; i < 8; i++) {
        O4[ba + sub + 4 * i] = make_float4(aa[i].x * ia, aa[i].y * ia, aa[i].z * ia, aa[i].w * ia);
        O4[bb + sub + 4 * i] = make_float4(ab[i].x * ib, ab[i].y * ib, ab[i].z * ib, ab[i].w * ib);
    }
}

// ---------------------------------------------------------------------------
// attn [b,nh,s,hd] -> ctx [b,s,h]
// ---------------------------------------------------------------------------
__global__ void transpose_kernel() {
    int idx = blockIdx.x * blockDim.x + threadIdx.x;
    int col4 = idx & 511;
    int row  = idx >> 9;
    int b = row >> 11, s = row & 2047;
    int nh = col4 >> 5, d4 = col4 & 31;
    ((float4*)g_ctx)[idx] =
        ((const float4*)g_attn)[((size_t)(b * NH_ + nh) * S_ + s) * 32 + d4];
}

// ---------------------------------------------------------------------------
// kernel_launch
// ---------------------------------------------------------------------------
extern "C" void kernel_launch(void* const* d_in, const int* in_sizes, int n_in,
                              void* d_out, int out_size)
{
    const float* x    = (const float*)d_in[0];
    const float* wqkv = (const float*)d_in[2];
    const float* wo   = (const float*)d_in[3];

    float *qkv_p, *ctx_p, *wqkvT_p, *woT_p;
    cudaGetSymbolAddress((void**)&qkv_p, g_qkv);
    cudaGetSymbolAddress((void**)&ctx_p, g_ctx);
    cudaGetSymbolAddress((void**)&wqkvT_p, g_wqkvT);
    cudaGetSymbolAddress((void**)&woT_p, g_woT);

    trig_kernel<<<(S_ * 64 + 255) / 256, 256>>>();
    wtrans_kernel<<<dim3(H_ / 32, NQKV / 32), dim3(32, 8)>>>(wqkv, wqkvT_p, H_, NQKV);
    wtrans_kernel<<<dim3(H_ / 32, H_ / 32), dim3(32, 8)>>>(wo, woT_p, H_, H_);

    gemm_bf16s<<<dim3(NQKV / 128, M_ / 128), 256>>>(x, wqkvT_p, qkv_p, M_, NQKV, H_);
    split_rope_kernel<<<(B_ * NH_ * S_ * 64) / 256, 256>>>();
    attn_kernel<<<dim3(S_ / 128, B_ * NH_), 256>>>();
    transpose_kernel<<<(M_ * H_ / 4) / 256, 256>>>();
    gemm_bf16s<<<dim3(H_ / 128, M_ / 128), 256>>>(ctx_p, woT_p, (float*)d_out, M_, H_, H_);
}

// round 9
// speedup vs baseline: 3.2766x; 1.6633x over previous
#include <cuda_runtime.h>
#include <cuda_bf16.h>
#include <cstdint>
#include <math.h>

// Problem constants
#define B_   2
#define S_   2048
#define H_   2048
#define NH_  16
#define HD_  128
#define M_   (B_ * S_)      // 4096
#define NQKV (3 * H_)       // 6144

// ---------------------------------------------------------------------------
// Scratch (device globals — allocation-free per harness rules)
// ---------------------------------------------------------------------------
__device__ __align__(256) float g_qkv[(size_t)M_ * NQKV];
__device__ __align__(256) float g_attn[(size_t)B_ * NH_ * S_ * HD_];
__device__ __align__(256) float g_ctx[(size_t)M_ * H_];
__device__ __align__(256) float g_wqkvT[(size_t)NQKV * H_];
__device__ __align__(256) float g_woT[(size_t)H_ * H_];
__device__ __align__(256) float g_cos[S_ * 64];
__device__ __align__(256) float g_sin[S_ * 64];
// MMA-ready fragment arrays (hi/lo bf16 split), 33.5 MB each
__device__ __align__(256) uint32_t g_qf[(size_t)32 * 128 * 2048];
__device__ __align__(256) uint32_t g_kf[(size_t)32 * 32 * 8192];
__device__ __align__(256) uint32_t g_vf[(size_t)32 * 32 * 8192];

// ---------------------------------------------------------------------------
// fp32 -> (hi, lo) bf16 split, 2 floats at a time, packed bf16x2
// ---------------------------------------------------------------------------
__device__ __forceinline__ void split2(float a, float b, uint32_t& hi, uint32_t& lo) {
    __nv_bfloat162 h = __floats2bfloat162_rn(a, b);
    float ra = a - __bfloat162float(h.x);
    float rb = b - __bfloat162float(h.y);
    __nv_bfloat162 l = __floats2bfloat162_rn(ra, rb);
    hi = *(uint32_t*)&h;
    lo = *(uint32_t*)&l;
}

// mma.sync m16n8k16 bf16 (row.col), fp32 accumulate
#define MMA16816(cr, a, b0r, b1r)                                             \
    asm volatile("mma.sync.aligned.m16n8k16.row.col.f32.bf16.bf16.f32 "       \
        "{%0,%1,%2,%3}, {%4,%5,%6,%7}, {%8,%9}, {%0,%1,%2,%3};"               \
        : "+f"((cr)[0]), "+f"((cr)[1]), "+f"((cr)[2]), "+f"((cr)[3])          \
        : "r"((a).x), "r"((a).y), "r"((a).z), "r"((a).w), "r"(b0r), "r"(b1r))

// ---------------------------------------------------------------------------
// RoPE trig table (fp32 phase to match jax, accurate trig)
// ---------------------------------------------------------------------------
__global__ void trig_kernel() {
    int idx = blockIdx.x * blockDim.x + threadIdx.x;
    if (idx >= S_ * 64) return;
    int s = idx >> 6, i = idx & 63;
    float invf = (float)pow(10000.0, -(double)i / 64.0);
    float th = (float)s * invf;
    g_cos[idx] = (float)cos((double)th);
    g_sin[idx] = (float)sin((double)th);
}

// ---------------------------------------------------------------------------
// Weight transpose: W[K,N] -> WT[N,K]
// ---------------------------------------------------------------------------
__global__ void wtrans_kernel(const float* __restrict__ W, float* __restrict__ WT,
                              int K, int N) {
    __shared__ float t[32][33];
    int k0 = blockIdx.x * 32, n0 = blockIdx.y * 32;
    int tx = threadIdx.x, ty = threadIdx.y;
    #pragma unroll
    for (int j = 0; j < 4; j++)
        t[ty + 8 * j][tx] = W[(size_t)(k0 + ty + 8 * j) * N + n0 + tx];
    __syncthreads();
    #pragma unroll
    for (int j = 0; j < 4; j++)
        WT[(size_t)(n0 + ty + 8 * j) * K + k0 + tx] = t[tx][ty + 8 * j];
}

// ---------------------------------------------------------------------------
// Split-precision bf16 mma.sync GEMM (unchanged from R6 — validated).
// ---------------------------------------------------------------------------
__global__ __launch_bounds__(256, 2) void gemm_bf16s(
    const float* __restrict__ A, const float* __restrict__ BT,
    float* __restrict__ C, int M, int N, int K)
{
    __shared__ uint32_t sh[8192];

    const int tid = threadIdx.x;
    const int wid = tid >> 5, lane = tid & 31;
    const int g = lane >> 2, tig = lane & 3;
    const int warp_m = wid >> 1, warp_n = wid & 1;
    const int row0 = blockIdx.y * 128, col0 = blockIdx.x * 128;

    float c[2][8][4] = {};

    for (int k0 = 0; k0 < K; k0 += 32) {
        __syncthreads();
        #pragma unroll
        for (int u = 0; u < 4; u++) {
            int idx = tid + 256 * u;
            int m = idx >> 3, cseg = idx & 7;
            float4 v = *(const float4*)(A + (size_t)(row0 + m) * K + k0 + cseg * 4);
            uint32_t h0, l0, h1, l1;
            split2(v.x, v.y, h0, l0);
            split2(v.z, v.w, h1, l1);
            int kl = cseg * 4;
            int tile_m = m >> 4, half_m = (m >> 3) & 1, gg = m & 7;
            int tile_k = kl >> 4, kk = kl & 15, half_k = kk >> 3, tg = (kk & 7) >> 1;
            int reg = half_m + 2 * half_k;
            int base = ((tile_m * 2 + tile_k) * 32 + gg * 4 + tg) * 4 + reg;
            sh[base] = h0;        sh[base + 4] = h1;
            sh[2048 + base] = l0; sh[2048 + base + 4] = l1;
        }
        #pragma unroll
        for (int u = 0; u < 4; u++) {
            int idx = tid + 256 * u;
            int n = idx >> 3, cseg = idx & 7;
            float4 v = *(const float4*)(BT + (size_t)(col0 + n) * K + k0 + cseg * 4);
            uint32_t h0, l0, h1, l1;
            split2(v.x, v.y, h0, l0);
            split2(v.z, v.w, h1, l1);
            int kl = cseg * 4;
            int tile_n = n >> 3, gg = n & 7;
            int tile_k = kl >> 4, kk = kl & 15, reg = kk >> 3, tg = (kk & 7) >> 1;
            int base = ((tile_n * 2 + tile_k) * 32 + gg * 4 + tg) * 2 + reg;
            sh[4096 + base] = h0; sh[4096 + base + 2] = h1;
            sh[6144 + base] = l0; sh[6144 + base + 2] = l1;
        }
        __syncthreads();

        #pragma unroll
        for (int tk = 0; tk < 2; tk++) {
            uint4 ahi[2], alo[2];
            #pragma unroll
            for (int i = 0; i < 2; i++) {
                int off = (((warp_m * 2 + i) * 2 + tk) * 32 + lane) * 4;
                ahi[i] = *(uint4*)&sh[off];
                alo[i] = *(uint4*)&sh[2048 + off];
            }
            #pragma unroll
            for (int j = 0; j < 8; j++) {
                int off = (((warp_n * 8 + j) * 2 + tk) * 32 + lane) * 2;
                uint32_t bh0 = sh[4096 + off], bh1 = sh[4096 + off + 1];
                uint32_t bl0 = sh[6144 + off], bl1 = sh[6144 + off + 1];
                #pragma unroll
                for (int i = 0; i < 2; i++) {
                    MMA16816(c[i][j], ahi[i], bh0, bh1);
                    MMA16816(c[i][j], ahi[i], bl0, bl1);
                    MMA16816(c[i][j], alo[i], bh0, bh1);
                }
            }
        }
    }

    #pragma unroll
    for (int i = 0; i < 2; i++) {
        int r0 = row0 + (warp_m * 2 + i) * 16 + g;
        #pragma unroll
        for (int j = 0; j < 8; j++) {
            int cc = col0 + (warp_n * 8 + j) * 8 + tig * 2;
            *(float2*)(C + (size_t)r0 * N + cc)       = make_float2(c[i][j][0], c[i][j][1]);
            *(float2*)(C + (size_t)(r0 + 8) * N + cc) = make_float2(c[i][j][2], c[i][j][3]);
        }
    }
}

// ---------------------------------------------------------------------------
// Prep: qkv -> RoPE'd Q/K/V in pre-permuted m16n8k16 fragment layouts (hi/lo).
// Block = (stile of 64 seq rows, head bh). Layout formulas identical to the
// validated gemm_bf16s slab builder.
//   g_qf per (bh, mq=s/16): [ks 0..7][lane][h0..h3, l0..l3]           (A frag)
//   g_kf per (bh, ktile=s/64): [tl 0..7][ks 0..7][lane][h0,h1,l0,l1]  (B frag)
//   g_vf per (bh, ktile): [t' 0..15][ks' 0..3][lane][h0,h1,l0,l1]     (B frag)
// ---------------------------------------------------------------------------
__global__ __launch_bounds__(256) void prep_kernel() {
    const int st = blockIdx.x, bh = blockIdx.y;
    const int b = bh >> 4, nh = bh & 15;
    const int s0 = st * 64;
    const int tid = threadIdx.x;
    __shared__ float vsm[64 * 132];

    // Phase 1: Q and K fragments (rope pairing (d, d+64) is within-thread)
    #pragma unroll
    for (int u = 0; u < 8; u++) {
        int i = tid + 256 * u;              // 0..2047
        int r = i >> 5, dg = i & 31;        // row in tile, dim-group
        int s = s0 + r;
        size_t base = (size_t)(b * S_ + s) * NQKV + nh * HD_;
        float2 qx = *(const float2*)&g_qkv[base + 2 * dg];
        float2 qy = *(const float2*)&g_qkv[base + 2 * dg + 64];
        float2 kx = *(const float2*)&g_qkv[base + H_ + 2 * dg];
        float2 ky = *(const float2*)&g_qkv[base + H_ + 2 * dg + 64];
        float c0 = g_cos[s * 64 + 2 * dg], c1 = g_cos[s * 64 + 2 * dg + 1];
        float n0 = g_sin[s * 64 + 2 * dg], n1 = g_sin[s * 64 + 2 * dg + 1];

        float qa0 = qx.x * c0 - qy.x * n0, qa1 = qx.y * c1 - qy.y * n1;
        float qb0 = qy.x * c0 + qx.x * n0, qb1 = qy.y * c1 + qx.y * n1;
        float ka0 = kx.x * c0 - ky.x * n0, ka1 = kx.y * c1 - ky.y * n1;
        float kb0 = ky.x * c0 + kx.x * n0, kb1 = ky.y * c1 + kx.y * n1;

        int mq = s >> 4, rr = s & 15;
        size_t qb_ = (size_t)(bh * 128 + mq) * 2048;
        int tl = (s >> 3) & 7, gk = s & 7;
        size_t kb_ = (size_t)(bh * 32 + st) * 8192 + (size_t)tl * 1024;

        uint32_t h, l;
        // pair p = dg (dims 2dg, 2dg+1)
        {
            int p = dg, ks = p >> 3, pl = p & 7;
            int lane = (rr & 7) * 4 + (pl & 3);
            int reg = (rr >> 3) + 2 * (pl >> 2);
            split2(qa0, qa1, h, l);
            size_t w = qb_ + (size_t)ks * 256 + lane * 8;
            g_qf[w + reg] = h; g_qf[w + 4 + reg] = l;
            int klane = gk * 4 + (pl & 3), kreg = pl >> 2;
            split2(ka0, ka1, h, l);
            size_t wk = kb_ + (size_t)ks * 128 + klane * 4;
            g_kf[wk + kreg] = h; g_kf[wk + 2 + kreg] = l;
        }
        // pair p = dg + 32 (dims 2dg+64, 2dg+65)
        {
            int p = dg + 32, ks = p >> 3, pl = p & 7;
            int lane = (rr & 7) * 4 + (pl & 3);
            int reg = (rr >> 3) + 2 * (pl >> 2);
            split2(qb0, qb1, h, l);
            size_t w = qb_ + (size_t)ks * 256 + lane * 8;
            g_qf[w + reg] = h; g_qf[w + 4 + reg] = l;
            int klane = gk * 4 + (pl & 3), kreg = pl >> 2;
            split2(kb0, kb1, h, l);
            size_t wk = kb_ + (size_t)ks * 128 + klane * 4;
            g_kf[wk + kreg] = h; g_kf[wk + 2 + kreg] = l;
        }
    }

    // Phase 2: stage V tile, then build V B-fragments (key-pairs cross rows)
    #pragma unroll
    for (int u = 0; u < 8; u++) {
        int i = tid + 256 * u;              // 2048 float4 = 64 rows x 32
        int r = i >> 5, c4 = i & 31;
        size_t base = (size_t)(b * S_ + s0 + r) * NQKV + nh * HD_ + 2 * H_;
        float4 v = *(const float4*)&g_qkv[base + 4 * c4];
        float* d = &vsm[r * 132 + 4 * c4];
        d[0] = v.x; d[1] = v.y; d[2] = v.z; d[3] = v.w;
    }
    __syncthreads();

    {
        int kp = tid >> 3, nb = tid & 7;    // keypair 0..31, dim low bits
        int ks2 = kp >> 3, tg2 = kp & 3, half = (kp >> 2) & 1;
        size_t vb_ = (size_t)(bh * 32 + st) * 8192;
        #pragma unroll
        for (int j = 0; j < 16; j++) {
            int n = nb + 8 * j;             // dim; t' = j, g = nb
            float va = vsm[2 * kp * 132 + n];
            float vv = vsm[(2 * kp + 1) * 132 + n];
            uint32_t h, l; split2(va, vv, h, l);
            int lane = nb * 4 + tg2;
            size_t w = vb_ + ((size_t)(j * 4 + ks2) * 32 + lane) * 4;
            g_vf[w + half] = h;
            g_vf[w + 2 + half] = l;
        }
    }
}

// ---------------------------------------------------------------------------
// MMA flash attention. Grid (16 q-tiles reversed, 32 heads), 256 threads.
// Warp wid owns q-rows [q0+16*wid, +16). K-tile = 64 keys. QK^T and PV both
// 3-term bf16 split. Online softmax in C-fragment registers (FA2 layout);
// score C-frag repacks directly into the PV A-frag.
// ---------------------------------------------------------------------------
#define ATTN_SMEM 65536
__global__ __launch_bounds__(256, 1) void attn_mma() {
    extern __shared__ uint32_t asm_[];
    uint32_t* ksm = asm_;            // 8192 words
    uint32_t* vsm = asm_ + 8192;     // 8192 words

    const int bh = blockIdx.y;
    const int qt = (int)(gridDim.x - 1 - blockIdx.x);   // heavy tiles first
    const int q0 = qt * 128;
    const int tid = threadIdx.x, wid = tid >> 5, lane = tid & 31;
    const int g = lane >> 2, tig = lane & 3;

    // Q fragments for this warp's m16 tile
    uint4 qhi[8], qlo[8];
    {
        const uint32_t* qf = g_qf + (size_t)(bh * 128 + (q0 >> 4) + wid) * 2048;
        #pragma unroll
        for (int ks = 0; ks < 8; ks++) {
            const uint32_t* p = qf + (ks * 32 + lane) * 8;
            qhi[ks] = *(const uint4*)p;
            qlo[ks] = *(const uint4*)(p + 4);
        }
    }

    float o[16][4];
    #pragma unroll
    for (int t = 0; t < 16; t++) { o[t][0] = o[t][1] = o[t][2] = o[t][3] = 0.f; }
    float ma = -1e30f, mb = -1e30f, la = 0.f, lb = 0.f;
    const int row_a = q0 + wid * 16 + g;
    const int row_b = row_a + 8;
    const float scale = 0.08838834764831845f;   // 1/sqrt(128)

    const int nkt = (q0 + 128) >> 6;
    for (int kt = 0; kt < nkt; kt++) {
        const uint4* gk = (const uint4*)(g_kf + (size_t)(bh * 32 + kt) * 8192);
        const uint4* gv = (const uint4*)(g_vf + (size_t)(bh * 32 + kt) * 8192);
        #pragma unroll
        for (int u = 0; u < 8; u++) {
            int i = tid + 256 * u;
            ((uint4*)ksm)[i] = gk[i];
            ((uint4*)vsm)[i] = gv[i];
        }
        __syncthreads();

        // scores: 8 n8-tiles x 8 k-steps x 3 terms
        float c[8][4];
        #pragma unroll
        for (int t = 0; t < 8; t++) { c[t][0] = c[t][1] = c[t][2] = c[t][3] = 0.f; }
        #pragma unroll
        for (int ks = 0; ks < 8; ks++) {
            #pragma unroll
            for (int t = 0; t < 8; t++) {
                uint4 kf = *(uint4*)&ksm[((t * 8 + ks) * 32 + lane) * 4];
                MMA16816(c[t], qhi[ks], kf.x, kf.y);   // hh
                MMA16816(c[t], qhi[ks], kf.z, kf.w);   // hl
                MMA16816(c[t], qlo[ks], kf.x, kf.y);   // lh
            }
        }

        // scale + causal mask + row maxima
        float mxa = -1e30f, mxb = -1e30f;
        const bool need_mask = (kt * 64 + 63 > q0 + wid * 16);
        #pragma unroll
        for (int t = 0; t < 8; t++) {
            int k0 = kt * 64 + t * 8 + 2 * tig;
            float s0 = c[t][0] * scale, s1 = c[t][1] * scale;
            float s2 = c[t][2] * scale, s3 = c[t][3] * scale;
            if (need_mask) {
                if (k0 > row_a)     s0 = -1e30f;
                if (k0 + 1 > row_a) s1 = -1e30f;
                if (k0 > row_b)     s2 = -1e30f;
                if (k0 + 1 > row_b) s3 = -1e30f;
            }
            c[t][0] = s0; c[t][1] = s1; c[t][2] = s2; c[t][3] = s3;
            mxa = fmaxf(mxa, fmaxf(s0, s1));
            mxb = fmaxf(mxb, fmaxf(s2, s3));
        }
        mxa = fmaxf(mxa, __shfl_xor_sync(0xffffffffu, mxa, 1));
        mxa = fmaxf(mxa, __shfl_xor_sync(0xffffffffu, mxa, 2));
        mxb = fmaxf(mxb, __shfl_xor_sync(0xffffffffu, mxb, 1));
        mxb = fmaxf(mxb, __shfl_xor_sync(0xffffffffu, mxb, 2));

        float mna = fmaxf(ma, mxa), mnb = fmaxf(mb, mxb);
        float cra = __expf(ma - mna), crb = __expf(mb - mnb);
        ma = mna; mb = mnb; la *= cra; lb *= crb;
        #pragma unroll
        for (int t = 0; t < 16; t++) {
            o[t][0] *= cra; o[t][1] *= cra;
            o[t][2] *= crb; o[t][3] *= crb;
        }

        // exp, l-accumulate, pack P into PV A-frags (hi/lo)
        uint4 ahi[4], alo[4];
        #pragma unroll
        for (int k2 = 0; k2 < 4; k2++) {
            int t0 = 2 * k2, t1 = 2 * k2 + 1;
            float p0 = __expf(c[t0][0] - ma), p1 = __expf(c[t0][1] - ma);
            float p2 = __expf(c[t0][2] - mb), p3 = __expf(c[t0][3] - mb);
            float p4 = __expf(c[t1][0] - ma), p5 = __expf(c[t1][1] - ma);
            float p6 = __expf(c[t1][2] - mb), p7 = __expf(c[t1][3] - mb);
            la += p0 + p1 + p4 + p5;
            lb += p2 + p3 + p6 + p7;
            split2(p0, p1, ahi[k2].x, alo[k2].x);
            split2(p2, p3, ahi[k2].y, alo[k2].y);
            split2(p4, p5, ahi[k2].z, alo[k2].z);
            split2(p6, p7, ahi[k2].w, alo[k2].w);
        }

        // PV: 16 n8 dim-tiles x 4 k-steps x 3 terms
        #pragma unroll
        for (int k2 = 0; k2 < 4; k2++) {
            #pragma unroll
            for (int t2 = 0; t2 < 16; t2++) {
                uint4 vf = *(uint4*)&vsm[((t2 * 4 + k2) * 32 + lane) * 4];
                MMA16816(o[t2], ahi[k2], vf.x, vf.y);
                MMA16816(o[t2], ahi[k2], vf.z, vf.w);
                MMA16816(o[t2], alo[k2], vf.x, vf.y);
            }
        }
        __syncthreads();
    }

    la += __shfl_xor_sync(0xffffffffu, la, 1);
    la += __shfl_xor_sync(0xffffffffu, la, 2);
    lb += __shfl_xor_sync(0xffffffffu, lb, 1);
    lb += __shfl_xor_sync(0xffffffffu, lb, 2);
    float ia = 1.f / la, ib = 1.f / lb;

    float* oa = g_attn + ((size_t)bh * S_ + row_a) * HD_;
    #pragma unroll
    for (int t2 = 0; t2 < 16; t2++) {
        int d = t2 * 8 + 2 * tig;
        *(float2*)(oa + d)            = make_float2(o[t2][0] * ia, o[t2][1] * ia);
        *(float2*)(oa + 8 * HD_ + d)  = make_float2(o[t2][2] * ib, o[t2][3] * ib);
    }
}

// ---------------------------------------------------------------------------
// attn [b,nh,s,hd] -> ctx [b,s,h]
// ---------------------------------------------------------------------------
__global__ void transpose_kernel() {
    int idx = blockIdx.x * blockDim.x + threadIdx.x;
    int col4 = idx & 511;
    int row  = idx >> 9;
    int b = row >> 11, s = row & 2047;
    int nh = col4 >> 5, d4 = col4 & 31;
    ((float4*)g_ctx)[idx] =
        ((const float4*)g_attn)[((size_t)(b * NH_ + nh) * S_ + s) * 32 + d4];
}

// ---------------------------------------------------------------------------
// kernel_launch
// ---------------------------------------------------------------------------
extern "C" void kernel_launch(void* const* d_in, const int* in_sizes, int n_in,
                              void* d_out, int out_size)
{
    const float* x    = (const float*)d_in[0];
    const float* wqkv = (const float*)d_in[2];
    const float* wo   = (const float*)d_in[3];

    float *qkv_p, *ctx_p, *wqkvT_p, *woT_p;
    cudaGetSymbolAddress((void**)&qkv_p, g_qkv);
    cudaGetSymbolAddress((void**)&ctx_p, g_ctx);
    cudaGetSymbolAddress((void**)&wqkvT_p, g_wqkvT);
    cudaGetSymbolAddress((void**)&woT_p, g_woT);

    cudaFuncSetAttribute(attn_mma, cudaFuncAttributeMaxDynamicSharedMemorySize, ATTN_SMEM);

    trig_kernel<<<(S_ * 64 + 255) / 256, 256>>>();
    wtrans_kernel<<<dim3(H_ / 32, NQKV / 32), dim3(32, 8)>>>(wqkv, wqkvT_p, H_, NQKV);
    wtrans_kernel<<<dim3(H_ / 32, H_ / 32), dim3(32, 8)>>>(wo, woT_p, H_, H_);

    gemm_bf16s<<<dim3(NQKV / 128, M_ / 128), 256>>>(x, wqkvT_p, qkv_p, M_, NQKV, H_);
    prep_kernel<<<dim3(32, 32), 256>>>();
    attn_mma<<<dim3(S_ / 128, B_ * NH_), 256, ATTN_SMEM>>>();
    transpose_kernel<<<(M_ * H_ / 4) / 256, 256>>>();
    gemm_bf16s<<<dim3(H_ / 128, M_ / 128), 256>>>(ctx_p, woT_p, (float*)d_out, M_, H_, H_);
}

// round 10
// speedup vs baseline: 3.9018x; 1.1908x over previous
#include <cuda_runtime.h>
#include <cuda_bf16.h>
#include <cstdint>
#include <math.h>

// Problem constants
#define B_   2
#define S_   2048
#define H_   2048
#define NH_  16
#define HD_  128
#define M_   (B_ * S_)      // 4096
#define NQKV (3 * H_)       // 6144

// ---------------------------------------------------------------------------
// Scratch (device globals — allocation-free per harness rules)
// ---------------------------------------------------------------------------
__device__ __align__(256) float g_qkv[(size_t)M_ * NQKV];
__device__ __align__(256) float g_cos[S_ * 64];
__device__ __align__(256) float g_sin[S_ * 64];
// attention fragment arrays (hi/lo bf16 split)
__device__ __align__(256) uint32_t g_qf[(size_t)32 * 128 * 2048];
__device__ __align__(256) uint32_t g_kf[(size_t)32 * 32 * 8192];
__device__ __align__(256) uint32_t g_vf[(size_t)32 * 32 * 8192];
// GEMM fragment arrays
__device__ __align__(256) uint32_t g_xf[(size_t)M_ * H_ / 2 * 2];      // x A-frags
__device__ __align__(256) uint32_t g_cf[(size_t)M_ * H_ / 2 * 2];      // ctx A-frags
__device__ __align__(256) uint32_t g_wqkvf[(size_t)NQKV * H_ / 2 * 2]; // Wqkv B-frags
__device__ __align__(256) uint32_t g_wof[(size_t)H_ * H_ / 2 * 2];     // Wo B-frags

// ---------------------------------------------------------------------------
// Helpers
// ---------------------------------------------------------------------------
__device__ __forceinline__ void split2(float a, float b, uint32_t& hi, uint32_t& lo) {
    __nv_bfloat162 h = __floats2bfloat162_rn(a, b);
    float ra = a - __bfloat162float(h.x);
    float rb = b - __bfloat162float(h.y);
    __nv_bfloat162 l = __floats2bfloat162_rn(ra, rb);
    hi = *(uint32_t*)&h;
    lo = *(uint32_t*)&l;
}
#define MMA16816(cr, a, b0r, b1r)                                             \
    asm volatile("mma.sync.aligned.m16n8k16.row.col.f32.bf16.bf16.f32 "       \
        "{%0,%1,%2,%3}, {%4,%5,%6,%7}, {%8,%9}, {%0,%1,%2,%3};"               \
        : "+f"((cr)[0]), "+f"((cr)[1]), "+f"((cr)[2]), "+f"((cr)[3])          \
        : "r"((a).x), "r"((a).y), "r"((a).z), "r"((a).w), "r"(b0r), "r"(b1r))

__device__ __forceinline__ uint32_t smem_u32(const void* p) {
    uint32_t a;
    asm("{ .reg .u64 t; cvta.to.shared.u64 t, %1; cvt.u32.u64 %0, t; }" : "=r"(a) : "l"(p));
    return a;
}
#define CP_ASYNC16(dst, src) \
    asm volatile("cp.async.cg.shared.global [%0], [%1], 16;" :: "r"(dst), "l"(src))
#define CP_COMMIT() asm volatile("cp.async.commit_group;" ::: "memory")
#define CP_WAIT1()  asm volatile("cp.async.wait_group 1;" ::: "memory")
#define CP_WAIT0()  asm volatile("cp.async.wait_group 0;" ::: "memory")

// ---------------------------------------------------------------------------
// RoPE trig table (fp32 phase to match jax, accurate trig)
// ---------------------------------------------------------------------------
__global__ void trig_kernel() {
    int idx = blockIdx.x * blockDim.x + threadIdx.x;
    if (idx >= S_ * 64) return;
    int s = idx >> 6, i = idx & 63;
    float invf = (float)pow(10000.0, -(double)i / 64.0);
    float th = (float)s * invf;
    g_cos[idx] = (float)cos((double)th);
    g_sin[idx] = (float)sin((double)th);
}

// ---------------------------------------------------------------------------
// Activation -> A-fragment slabs.
// AF[((mt*(K/16)+kt)*32 + lane)*8 + reg], reg 0-3 hi, 4-7 lo.
// (m,k): lane = (m&7)*4 + ((k&7)>>1), reg = ((m>>3)&1) + 2*((k&15)>>3).
// ---------------------------------------------------------------------------
__global__ __launch_bounds__(256) void afrag_kernel(
    const float* __restrict__ A, uint32_t* __restrict__ AF, int M, int K)
{
    int idx = blockIdx.x * blockDim.x + threadIdx.x;     // over M*K/4
    int m = idx / (K >> 2), c4 = idx % (K >> 2);
    int k = 4 * c4;
    float4 v = *(const float4*)(A + (size_t)m * K + k);
    uint32_t h0, l0, h1, l1;
    split2(v.x, v.y, h0, l0);
    split2(v.z, v.w, h1, l1);
    int kt = k >> 4, kk = k & 15, tg = (kk & 7) >> 1, half_k = kk >> 3;
    int lane = (m & 7) * 4 + tg;
    int reg = ((m >> 3) & 1) + 2 * half_k;
    size_t base = (((size_t)(m >> 4) * (K >> 4) + kt) * 32 + lane) * 8 + reg;
    AF[base] = h0;     AF[base + 4] = l0;
    AF[base + 8] = h1; AF[base + 12] = l1;   // next tg -> lane+1 -> +8 words
}

// ---------------------------------------------------------------------------
// Weight W[K,N] -> B-fragment slabs (transpose + split + permute, one shot).
// BF[((nt*(K/16)+kt)*32 + lane)*4 + reg], reg 0-1 hi, 2-3 lo.
// (n,k): lane = (n&7)*4 + ((k&7)>>1), reg = (k&15)>>3.
// ---------------------------------------------------------------------------
__global__ void wfrag_kernel(const float* __restrict__ W, uint32_t* __restrict__ BF,
                             int K, int N) {
    __shared__ float t[32][33];
    int k0 = blockIdx.x * 32, n0 = blockIdx.y * 32;
    int tx = threadIdx.x, ty = threadIdx.y;   // 32 x 8
    #pragma unroll
    for (int j = 0; j < 4; j++)
        t[ty + 8 * j][tx] = W[(size_t)(k0 + ty + 8 * j) * N + n0 + tx];
    __syncthreads();
    int id = ty * 32 + tx;
    #pragma unroll
    for (int u = 0; u < 2; u++) {
        int pid = id + 256 * u;               // 0..511
        int n_l = pid & 31, kp = pid >> 5;
        int k_l = 2 * kp;
        float va = t[k_l][n_l], vb = t[k_l + 1][n_l];
        uint32_t h, l; split2(va, vb, h, l);
        int n = n0 + n_l, k = k0 + k_l;
        int nt = n >> 3, gg = n & 7;
        int kt = k >> 4, kk = k & 15, reg = kk >> 3, tg = (kk & 7) >> 1;
        int lane = gg * 4 + tg;
        size_t w = (((size_t)nt * (K >> 4) + kt) * 32 + lane) * 4;
        BF[w + reg] = h;
        BF[w + 2 + reg] = l;
    }
}

// ---------------------------------------------------------------------------
// Fragment GEMM: C[M,N] = A@W from precomputed frag slabs, cp.async 2-stage.
// CTA 128x128, 8 warps (4x2), warp tile 32x64, K-step 32. 3-term hi/lo split.
// smem per stage: A 4096 words (16KB) + B 4096 words (16KB); 2 stages = 64KB.
// ---------------------------------------------------------------------------
#define GEMM_SMEM 65536
__global__ __launch_bounds__(256, 2) void gemm_frag(
    const uint32_t* __restrict__ AF, const uint32_t* __restrict__ BF,
    float* __restrict__ C, int M, int N, int K)
{
    extern __shared__ uint32_t sh[];
    const uint32_t sb = smem_u32(sh);
    const int tid = threadIdx.x;
    const int wid = tid >> 5, lane = tid & 31;
    const int g = lane >> 2, tig = lane & 3;
    const int warp_m = wid >> 1, warp_n = wid & 1;
    const int mt0 = blockIdx.y * 8, nt0 = blockIdx.x * 16;
    const int KT = K >> 4;
    const int NIT = K >> 5;

    float c[2][8][4] = {};

    // stage copy: A 1024 16B-chunks + B 1024 16B-chunks, 8 cp.async/thread
    auto do_copy = [&](int st, int it) {
        const int kt0 = it * 2;
        uint32_t sbase = sb + st * 32768;
        #pragma unroll
        for (int u = 0; u < 4; u++) {
            int i = tid + 256 * u;
            int slab = i >> 6, within = i & 63;
            int mt_l = slab >> 1, kt_l = slab & 1;
            const uint32_t* src =
                AF + (((size_t)(mt0 + mt_l) * KT + kt0 + kt_l) * 256 + within * 4);
            CP_ASYNC16(sbase + (slab * 256 + within * 4) * 4, src);
        }
        #pragma unroll
        for (int u = 0; u < 4; u++) {
            int i = tid + 256 * u;
            int slab = i >> 5, within = i & 31;
            int nt_l = slab >> 1, kt_l = slab & 1;
            const uint32_t* src =
                BF + (((size_t)(nt0 + nt_l) * KT + kt0 + kt_l) * 128 + within * 4);
            CP_ASYNC16(sbase + 16384 + (slab * 128 + within * 4) * 4, src);
        }
    };

    do_copy(0, 0);
    CP_COMMIT();

    for (int it = 0; it < NIT; it++) {
        if (it + 1 < NIT) { do_copy((it + 1) & 1, it + 1); CP_COMMIT(); CP_WAIT1(); }
        else              { CP_WAIT0(); }
        __syncthreads();

        const uint32_t* s = sh + (it & 1) * 8192;
        #pragma unroll
        for (int tk = 0; tk < 2; tk++) {
            uint4 ahi[2], alo[2];
            #pragma unroll
            for (int i = 0; i < 2; i++) {
                int off = (((warp_m * 2 + i) * 2 + tk) * 32 + lane) * 8;
                ahi[i] = *(const uint4*)&s[off];
                alo[i] = *(const uint4*)&s[off + 4];
            }
            #pragma unroll
            for (int j = 0; j < 8; j++) {
                int off = 4096 + (((warp_n * 8 + j) * 2 + tk) * 32 + lane) * 4;
                uint4 bf = *(const uint4*)&s[off];
                #pragma unroll
                for (int i = 0; i < 2; i++) {
                    MMA16816(c[i][j], ahi[i], bf.x, bf.y);   // hh
                    MMA16816(c[i][j], ahi[i], bf.z, bf.w);   // hl
                    MMA16816(c[i][j], alo[i], bf.x, bf.y);   // lh
                }
            }
        }
        __syncthreads();
    }

    const int row0 = mt0 * 16, col0 = nt0 * 8;
    #pragma unroll
    for (int i = 0; i < 2; i++) {
        int r0 = row0 + (warp_m * 2 + i) * 16 + g;
        #pragma unroll
        for (int j = 0; j < 8; j++) {
            int cc = col0 + (warp_n * 8 + j) * 8 + tig * 2;
            *(float2*)(C + (size_t)r0 * N + cc)       = make_float2(c[i][j][0], c[i][j][1]);
            *(float2*)(C + (size_t)(r0 + 8) * N + cc) = make_float2(c[i][j][2], c[i][j][3]);
        }
    }
}

// ---------------------------------------------------------------------------
// Prep: qkv -> RoPE'd Q/K/V attention fragments (unchanged from R9).
// ---------------------------------------------------------------------------
__global__ __launch_bounds__(256) void prep_kernel() {
    const int st = blockIdx.x, bh = blockIdx.y;
    const int b = bh >> 4, nh = bh & 15;
    const int s0 = st * 64;
    const int tid = threadIdx.x;
    __shared__ float vsm[64 * 132];

    #pragma unroll
    for (int u = 0; u < 8; u++) {
        int i = tid + 256 * u;
        int r = i >> 5, dg = i & 31;
        int s = s0 + r;
        size_t base = (size_t)(b * S_ + s) * NQKV + nh * HD_;
        float2 qx = *(const float2*)&g_qkv[base + 2 * dg];
        float2 qy = *(const float2*)&g_qkv[base + 2 * dg + 64];
        float2 kx = *(const float2*)&g_qkv[base + H_ + 2 * dg];
        float2 ky = *(const float2*)&g_qkv[base + H_ + 2 * dg + 64];
        float c0 = g_cos[s * 64 + 2 * dg], c1 = g_cos[s * 64 + 2 * dg + 1];
        float n0 = g_sin[s * 64 + 2 * dg], n1 = g_sin[s * 64 + 2 * dg + 1];

        float qa0 = qx.x * c0 - qy.x * n0, qa1 = qx.y * c1 - qy.y * n1;
        float qb0 = qy.x * c0 + qx.x * n0, qb1 = qy.y * c1 + qx.y * n1;
        float ka0 = kx.x * c0 - ky.x * n0, ka1 = kx.y * c1 - ky.y * n1;
        float kb0 = ky.x * c0 + kx.x * n0, kb1 = ky.y * c1 + kx.y * n1;

        int mq = s >> 4, rr = s & 15;
        size_t qb_ = (size_t)(bh * 128 + mq) * 2048;
        int tl = (s >> 3) & 7, gk = s & 7;
        size_t kb_ = (size_t)(bh * 32 + st) * 8192 + (size_t)tl * 1024;

        uint32_t h, l;
        {
            int p = dg, ks = p >> 3, pl = p & 7;
            int lane = (rr & 7) * 4 + (pl & 3);
            int reg = (rr >> 3) + 2 * (pl >> 2);
            split2(qa0, qa1, h, l);
            size_t w = qb_ + (size_t)ks * 256 + lane * 8;
            g_qf[w + reg] = h; g_qf[w + 4 + reg] = l;
            int klane = gk * 4 + (pl & 3), kreg = pl >> 2;
            split2(ka0, ka1, h, l);
            size_t wk = kb_ + (size_t)ks * 128 + klane * 4;
            g_kf[wk + kreg] = h; g_kf[wk + 2 + kreg] = l;
        }
        {
            int p = dg + 32, ks = p >> 3, pl = p & 7;
            int lane = (rr & 7) * 4 + (pl & 3);
            int reg = (rr >> 3) + 2 * (pl >> 2);
            split2(qb0, qb1, h, l);
            size_t w = qb_ + (size_t)ks * 256 + lane * 8;
            g_qf[w + reg] = h; g_qf[w + 4 + reg] = l;
            int klane = gk * 4 + (pl & 3), kreg = pl >> 2;
            split2(kb0, kb1, h, l);
            size_t wk = kb_ + (size_t)ks * 128 + klane * 4;
            g_kf[wk + kreg] = h; g_kf[wk + 2 + kreg] = l;
        }
    }

    #pragma unroll
    for (int u = 0; u < 8; u++) {
        int i = tid + 256 * u;
        int r = i >> 5, c4 = i & 31;
        size_t base = (size_t)(b * S_ + s0 + r) * NQKV + nh * HD_ + 2 * H_;
        float4 v = *(const float4*)&g_qkv[base + 4 * c4];
        float* d = &vsm[r * 132 + 4 * c4];
        d[0] = v.x; d[1] = v.y; d[2] = v.z; d[3] = v.w;
    }
    __syncthreads();

    {
        int kp = tid >> 3, nb = tid & 7;
        int ks2 = kp >> 3, tg2 = kp & 3, half = (kp >> 2) & 1;
        size_t vb_ = (size_t)(bh * 32 + st) * 8192;
        #pragma unroll
        for (int j = 0; j < 16; j++) {
            int n = nb + 8 * j;
            float va = vsm[2 * kp * 132 + n];
            float vv = vsm[(2 * kp + 1) * 132 + n];
            uint32_t h, l; split2(va, vv, h, l);
            int lane = nb * 4 + tg2;
            size_t w = vb_ + ((size_t)(j * 4 + ks2) * 32 + lane) * 4;
            g_vf[w + half] = h;
            g_vf[w + 2 + half] = l;
        }
    }
}

// ---------------------------------------------------------------------------
// MMA flash attention, cp.async double-buffered K/V tiles; epilogue writes
// GEMM2 A-fragments (g_cf) directly — no ctx tensor, no transpose kernel.
// ---------------------------------------------------------------------------
#define ATTN_SMEM 131072
__global__ __launch_bounds__(256, 1) void attn_mma() {
    extern __shared__ uint32_t asm_[];   // stage: K 8192 + V 8192 words (64KB)

    const int bh = blockIdx.y;
    const int qt = (int)(gridDim.x - 1 - blockIdx.x);
    const int q0 = qt * 128;
    const int tid = threadIdx.x, wid = tid >> 5, lane = tid & 31;
    const int g = lane >> 2, tig = lane & 3;
    const uint32_t sb = smem_u32(asm_);

    uint4 qhi[8], qlo[8];
    {
        const uint32_t* qf = g_qf + (size_t)(bh * 128 + (q0 >> 4) + wid) * 2048;
        #pragma unroll
        for (int ks = 0; ks < 8; ks++) {
            const uint32_t* p = qf + (ks * 32 + lane) * 8;
            qhi[ks] = *(const uint4*)p;
            qlo[ks] = *(const uint4*)(p + 4);
        }
    }

    float o[16][4];
    #pragma unroll
    for (int t = 0; t < 16; t++) { o[t][0] = o[t][1] = o[t][2] = o[t][3] = 0.f; }
    float ma = -1e30f, mb = -1e30f, la = 0.f, lb = 0.f;
    const int row_a = q0 + wid * 16 + g;
    const int row_b = row_a + 8;
    const float scale = 0.08838834764831845f;

    const int nkt = (q0 + 128) >> 6;

    auto do_copy = [&](int st, int kt) {
        const uint4* gk = (const uint4*)(g_kf + (size_t)(bh * 32 + kt) * 8192);
        const uint4* gv = (const uint4*)(g_vf + (size_t)(bh * 32 + kt) * 8192);
        uint32_t base = sb + st * 65536;
        #pragma unroll
        for (int u = 0; u < 8; u++) {
            int i = tid + 256 * u;
            CP_ASYNC16(base + i * 16, gk + i);
            CP_ASYNC16(base + 32768 + i * 16, gv + i);
        }
    };

    do_copy(0, 0);
    CP_COMMIT();

    for (int kt = 0; kt < nkt; kt++) {
        if (kt + 1 < nkt) { do_copy((kt + 1) & 1, kt + 1); CP_COMMIT(); CP_WAIT1(); }
        else              { CP_WAIT0(); }
        __syncthreads();
        const uint32_t* ksm = asm_ + (kt & 1) * 16384;
        const uint32_t* vsm = ksm + 8192;

        float c[8][4];
        #pragma unroll
        for (int t = 0; t < 8; t++) { c[t][0] = c[t][1] = c[t][2] = c[t][3] = 0.f; }
        #pragma unroll
        for (int ks = 0; ks < 8; ks++) {
            #pragma unroll
            for (int t = 0; t < 8; t++) {
                uint4 kf = *(const uint4*)&ksm[((t * 8 + ks) * 32 + lane) * 4];
                MMA16816(c[t], qhi[ks], kf.x, kf.y);
                MMA16816(c[t], qhi[ks], kf.z, kf.w);
                MMA16816(c[t], qlo[ks], kf.x, kf.y);
            }
        }

        float mxa = -1e30f, mxb = -1e30f;
        const bool need_mask = (kt * 64 + 63 > q0 + wid * 16);
        #pragma unroll
        for (int t = 0; t < 8; t++) {
            int k0 = kt * 64 + t * 8 + 2 * tig;
            float s0 = c[t][0] * scale, s1 = c[t][1] * scale;
            float s2 = c[t][2] * scale, s3 = c[t][3] * scale;
            if (need_mask) {
                if (k0 > row_a)     s0 = -1e30f;
                if (k0 + 1 > row_a) s1 = -1e30f;
                if (k0 > row_b)     s2 = -1e30f;
                if (k0 + 1 > row_b) s3 = -1e30f;
            }
            c[t][0] = s0; c[t][1] = s1; c[t][2] = s2; c[t][3] = s3;
            mxa = fmaxf(mxa, fmaxf(s0, s1));
            mxb = fmaxf(mxb, fmaxf(s2, s3));
        }
        mxa = fmaxf(mxa, __shfl_xor_sync(0xffffffffu, mxa, 1));
        mxa = fmaxf(mxa, __shfl_xor_sync(0xffffffffu, mxa, 2));
        mxb = fmaxf(mxb, __shfl_xor_sync(0xffffffffu, mxb, 1));
        mxb = fmaxf(mxb, __shfl_xor_sync(0xffffffffu, mxb, 2));

        float mna = fmaxf(ma, mxa), mnb = fmaxf(mb, mxb);
        float cra = __expf(ma - mna), crb = __expf(mb - mnb);
        ma = mna; mb = mnb; la *= cra; lb *= crb;
        #pragma unroll
        for (int t = 0; t < 16; t++) {
            o[t][0] *= cra; o[t][1] *= cra;
            o[t][2] *= crb; o[t][3] *= crb;
        }

        uint4 ahi[4], alo[4];
        #pragma unroll
        for (int k2 = 0; k2 < 4; k2++) {
            int t0 = 2 * k2, t1 = 2 * k2 + 1;
            float p0 = __expf(c[t0][0] - ma), p1 = __expf(c[t0][1] - ma);
            float p2 = __expf(c[t0][2] - mb), p3 = __expf(c[t0][3] - mb);
            float p4 = __expf(c[t1][0] - ma), p5 = __expf(c[t1][1] - ma);
            float p6 = __expf(c[t1][2] - mb), p7 = __expf(c[t1][3] - mb);
            la += p0 + p1 + p4 + p5;
            lb += p2 + p3 + p6 + p7;
            split2(p0, p1, ahi[k2].x, alo[k2].x);
            split2(p2, p3, ahi[k2].y, alo[k2].y);
            split2(p4, p5, ahi[k2].z, alo[k2].z);
            split2(p6, p7, ahi[k2].w, alo[k2].w);
        }

        #pragma unroll
        for (int k2 = 0; k2 < 4; k2++) {
            #pragma unroll
            for (int t2 = 0; t2 < 16; t2++) {
                uint4 vf = *(const uint4*)&vsm[((t2 * 4 + k2) * 32 + lane) * 4];
                MMA16816(o[t2], ahi[k2], vf.x, vf.y);
                MMA16816(o[t2], ahi[k2], vf.z, vf.w);
                MMA16816(o[t2], alo[k2], vf.x, vf.y);
            }
        }
        __syncthreads();
    }

    la += __shfl_xor_sync(0xffffffffu, la, 1);
    la += __shfl_xor_sync(0xffffffffu, la, 2);
    lb += __shfl_xor_sync(0xffffffffu, lb, 1);
    lb += __shfl_xor_sync(0xffffffffu, lb, 2);
    float ia = 1.f / la, ib = 1.f / lb;

    // Write GEMM2 A-fragments directly: token row r = b*S + s, k-dim h = nh*128+d.
    // mt = r>>4 (= b*128 + (s>>4)), kt = nh*8 + (t2>>1), lane = own lane,
    // reg = rowhalf + 2*(t2&1).
    const int b = bh >> 4, nh = bh & 15;
    const int mt = b * 128 + ((q0 >> 4) + wid);
    #pragma unroll
    for (int t2 = 0; t2 < 16; t2++) {
        int kt2 = nh * 8 + (t2 >> 1);
        size_t base = (((size_t)mt * 128 + kt2) * 32 + lane) * 8 + 2 * (t2 & 1);
        uint32_t h, l;
        split2(o[t2][0] * ia, o[t2][1] * ia, h, l);
        g_cf[base] = h;     g_cf[base + 4] = l;
        split2(o[t2][2] * ib, o[t2][3] * ib, h, l);
        g_cf[base + 1] = h; g_cf[base + 5] = l;
    }
}

// ---------------------------------------------------------------------------
// kernel_launch
// ---------------------------------------------------------------------------
extern "C" void kernel_launch(void* const* d_in, const int* in_sizes, int n_in,
                              void* d_out, int out_size)
{
    const float* x    = (const float*)d_in[0];
    const float* wqkv = (const float*)d_in[2];
    const float* wo   = (const float*)d_in[3];

    float* qkv_p;
    uint32_t *xf_p, *cf_p, *wqkvf_p, *wof_p;
    cudaGetSymbolAddress((void**)&qkv_p, g_qkv);
    cudaGetSymbolAddress((void**)&xf_p, g_xf);
    cudaGetSymbolAddress((void**)&cf_p, g_cf);
    cudaGetSymbolAddress((void**)&wqkvf_p, g_wqkvf);
    cudaGetSymbolAddress((void**)&wof_p, g_wof);

    cudaFuncSetAttribute(gemm_frag, cudaFuncAttributeMaxDynamicSharedMemorySize, GEMM_SMEM);
    cudaFuncSetAttribute(attn_mma, cudaFuncAttributeMaxDynamicSharedMemorySize, ATTN_SMEM);

    trig_kernel<<<(S_ * 64 + 255) / 256, 256>>>();
    wfrag_kernel<<<dim3(H_ / 32, NQKV / 32), dim3(32, 8)>>>(wqkv, wqkvf_p, H_, NQKV);
    wfrag_kernel<<<dim3(H_ / 32, H_ / 32), dim3(32, 8)>>>(wo, wof_p, H_, H_);
    afrag_kernel<<<(M_ * H_ / 4) / 256, 256>>>(x, xf_p, M_, H_);

    gemm_frag<<<dim3(NQKV / 128, M_ / 128), 256, GEMM_SMEM>>>(xf_p, wqkvf_p, qkv_p, M_, NQKV, H_);
    prep_kernel<<<dim3(32, 32), 256>>>();
    attn_mma<<<dim3(S_ / 128, B_ * NH_), 256, ATTN_SMEM>>>();
    gemm_frag<<<dim3(H_ / 128, M_ / 128), 256, GEMM_SMEM>>>(cf_p, wof_p, (float*)d_out, M_, H_, H_);
}